// round 13
// baseline (speedup 1.0000x reference)
#include <cuda_runtime.h>
#include <math.h>
#include <stdint.h>

#define NN   50000
#define EE   800000
#define GG   2000
#define FIN  34
#define HIDW 256
#define NH   8
#define HD   32
#define NL   5

// ---------------- scratch (device globals; no allocation allowed) ----------------
__device__ float g_h [NN * HIDW];
__device__ float g_b1[NN * HIDW];
__device__ float g_b2[NN * HIDW];
__device__ float g_b3[NN * HIDW];
__device__ float g_b4[NN * HIDW];
__device__ float g_ge[GG * 2 * HIDW];
__device__ float g_go[GG * 2 * HIDW];

// CSR scratch
__device__ int g_deg[NN];
__device__ int g_rowptr[NN];
__device__ int g_cur[NN];      // after scatter: row end
__device__ int g_bsum[256];
__device__ int g_esrc[EE];

// ---------------- helpers ----------------
__device__ __forceinline__ float warpSum(float v) {
#pragma unroll
    for (int o = 16; o > 0; o >>= 1) v += __shfl_xor_sync(0xffffffffu, v, o);
    return v;
}

__device__ __forceinline__ float gelu_exact(float x) {
    return 0.5f * x * (1.0f + erff(x * 0.70710678118654752440f));
}

__device__ __forceinline__ void tf32_split(float f, float& hi, float& lo) {
    uint32_t h;
    asm("cvt.rna.tf32.f32 %0, %1;" : "=r"(h) : "f"(f));
    hi = __uint_as_float(h);
    float r = f - hi;
    uint32_t l;
    asm("cvt.rna.tf32.f32 %0, %1;" : "=r"(l) : "f"(r));
    lo = __uint_as_float(l);
}

#define MMA_TF32(d, a0, a1, a2, a3, b0, b1)                                   \
    asm volatile("mma.sync.aligned.m16n8k8.row.col.f32.tf32.tf32.f32 "        \
                 "{%0,%1,%2,%3}, {%4,%5,%6,%7}, {%8,%9}, {%0,%1,%2,%3};"      \
                 : "+f"(d[0]), "+f"(d[1]), "+f"(d[2]), "+f"(d[3])             \
                 : "r"(__float_as_uint(a0)), "r"(__float_as_uint(a1)),        \
                   "r"(__float_as_uint(a2)), "r"(__float_as_uint(a3)),        \
                   "r"(__float_as_uint(b0)), "r"(__float_as_uint(b1)))

// ---------------- 3xTF32 tensor-core GEMM: C = A[M,K] @ W[K,N] + bias -------
// Block 128x128, BK=16, 8 warps (warp tile 64x32), m16n8k8 tf32 MMA.
// 3xTF32: a,b split hi/lo; acc += ahi*bhi + ahi*blo + alo*bhi  (~fp32 accuracy)
#define GBM 128
#define GBN 128
#define GBK 16
#define ASTR 20    // As row stride (floats): 16 + 4 pad -> conflict-free frags
#define BSTR 132   // Bs row stride (floats): 128 + 4 pad

__global__ __launch_bounds__(256, 1)
void gemm_tf32(const float* __restrict__ A, const float* __restrict__ W,
               const float* __restrict__ bias, float* __restrict__ C,
               int M, int K, int Ncol)
{
    __shared__ float AsH[GBM * ASTR], AsL[GBM * ASTR];
    __shared__ float BsH[GBK * BSTR], BsL[GBK * BSTR];

    const int tid = threadIdx.x, lane = tid & 31, w = tid >> 5;
    const int wm = (w >> 2) * 64;        // 0 or 64
    const int wn = (w & 3) * 32;         // 0,32,64,96
    const int bx = blockIdx.x * GBN, by = blockIdx.y * GBM;
    const bool alig = ((K & 3) == 0);

    float acc[4][4][4];
#pragma unroll
    for (int i = 0; i < 4; i++)
#pragma unroll
        for (int j = 0; j < 4; j++)
#pragma unroll
            for (int r = 0; r < 4; r++) acc[i][j][r] = 0.f;

    float av[2][4], bv[2][4];
    const int nsteps = (K + GBK - 1) / GBK;

    auto loadAB = [&](int s) {
        int k0 = s * GBK;
#pragma unroll
        for (int r = 0; r < 2; r++) {
            int i = tid + r * 256;
            int m = i >> 2, kq = i & 3;
            int gm = by + m, gk = k0 + kq * 4;
            if (alig && gm < M && gk + 4 <= K) {
                float4 t = *(const float4*)(A + (size_t)gm * K + gk);
                av[r][0] = t.x; av[r][1] = t.y; av[r][2] = t.z; av[r][3] = t.w;
            } else {
#pragma unroll
                for (int c = 0; c < 4; c++)
                    av[r][c] = (gm < M && gk + c < K) ? A[(size_t)gm * K + gk + c] : 0.f;
            }
        }
#pragma unroll
        for (int r = 0; r < 2; r++) {
            int i = tid + r * 256;
            int k = i >> 5, nq = i & 31;
            int gk = k0 + k, gn = bx + nq * 4;
            if (gk < K) {
                float4 t = *(const float4*)(W + (size_t)gk * Ncol + gn);
                bv[r][0] = t.x; bv[r][1] = t.y; bv[r][2] = t.z; bv[r][3] = t.w;
            } else {
                bv[r][0] = bv[r][1] = bv[r][2] = bv[r][3] = 0.f;
            }
        }
    };

    loadAB(0);

    for (int s = 0; s < nsteps; s++) {
        // stage prefetched tile into smem with hi/lo split
#pragma unroll
        for (int r = 0; r < 2; r++) {
            int i = tid + r * 256;
            int m = i >> 2, kq = i & 3;
#pragma unroll
            for (int c = 0; c < 4; c++) {
                float hi, lo; tf32_split(av[r][c], hi, lo);
                AsH[m * ASTR + kq * 4 + c] = hi;
                AsL[m * ASTR + kq * 4 + c] = lo;
            }
        }
#pragma unroll
        for (int r = 0; r < 2; r++) {
            int i = tid + r * 256;
            int k = i >> 5, nq = i & 31;
#pragma unroll
            for (int c = 0; c < 4; c++) {
                float hi, lo; tf32_split(bv[r][c], hi, lo);
                BsH[k * BSTR + nq * 4 + c] = hi;
                BsL[k * BSTR + nq * 4 + c] = lo;
            }
        }
        __syncthreads();

        if (s + 1 < nsteps) loadAB(s + 1);

#pragma unroll
        for (int kk = 0; kk < 2; kk++) {
            const int kb = kk * 8;
            float ah[4][4], al[4][4];
#pragma unroll
            for (int mt = 0; mt < 4; mt++) {
                int rb = wm + mt * 16 + (lane >> 2);
                int ci = kb + (lane & 3);
                ah[mt][0] = AsH[rb * ASTR + ci];
                ah[mt][1] = AsH[(rb + 8) * ASTR + ci];
                ah[mt][2] = AsH[rb * ASTR + ci + 4];
                ah[mt][3] = AsH[(rb + 8) * ASTR + ci + 4];
                al[mt][0] = AsL[rb * ASTR + ci];
                al[mt][1] = AsL[(rb + 8) * ASTR + ci];
                al[mt][2] = AsL[rb * ASTR + ci + 4];
                al[mt][3] = AsL[(rb + 8) * ASTR + ci + 4];
            }
            float bh[4][2], bl[4][2];
#pragma unroll
            for (int nt = 0; nt < 4; nt++) {
                int cb = wn + nt * 8 + (lane >> 2);
                int kr = kb + (lane & 3);
                bh[nt][0] = BsH[kr * BSTR + cb];
                bh[nt][1] = BsH[(kr + 4) * BSTR + cb];
                bl[nt][0] = BsL[kr * BSTR + cb];
                bl[nt][1] = BsL[(kr + 4) * BSTR + cb];
            }
#pragma unroll
            for (int mt = 0; mt < 4; mt++)
#pragma unroll
                for (int nt = 0; nt < 4; nt++) {
                    MMA_TF32(acc[mt][nt], ah[mt][0], ah[mt][1], ah[mt][2], ah[mt][3],
                             bh[nt][0], bh[nt][1]);
                    MMA_TF32(acc[mt][nt], ah[mt][0], ah[mt][1], ah[mt][2], ah[mt][3],
                             bl[nt][0], bl[nt][1]);
                    MMA_TF32(acc[mt][nt], al[mt][0], al[mt][1], al[mt][2], al[mt][3],
                             bh[nt][0], bh[nt][1]);
                }
        }
        __syncthreads();
    }

    // epilogue
#pragma unroll
    for (int mt = 0; mt < 4; mt++) {
        int gm0 = by + wm + mt * 16 + (lane >> 2);
        int gm1 = gm0 + 8;
#pragma unroll
        for (int nt = 0; nt < 4; nt++) {
            int gn = bx + wn + nt * 8 + 2 * (lane & 3);
            float b0 = bias[gn], b1 = bias[gn + 1];
            if (gm0 < M) {
                float2 o = make_float2(acc[mt][nt][0] + b0, acc[mt][nt][1] + b1);
                *(float2*)(C + (size_t)gm0 * Ncol + gn) = o;
            }
            if (gm1 < M) {
                float2 o = make_float2(acc[mt][nt][2] + b0, acc[mt][nt][3] + b1);
                *(float2*)(C + (size_t)gm1 * Ncol + gn) = o;
            }
        }
    }
}

// ---------------- fused: out = (gelu?)(LN(x)) ----------------
__global__ void ln_act_kernel(const float* __restrict__ x,
                              const float* __restrict__ gamma, const float* __restrict__ beta,
                              float* __restrict__ out,
                              int rows, int width, int do_gelu)
{
    int warp = (blockIdx.x * blockDim.x + threadIdx.x) >> 5;
    int lane = threadIdx.x & 31;
    if (warp >= rows) return;
    const int per = width / 32;
    float v[16];
    size_t base = (size_t)warp * width;
    float s = 0.f, ss = 0.f;
#pragma unroll 4
    for (int i = 0; i < per; i++) {
        float t = x[base + lane + i * 32];
        v[i] = t; s += t; ss += t * t;
    }
    s = warpSum(s); ss = warpSum(ss);
    float mean = s / width;
    float inv = rsqrtf(ss / width - mean * mean + 1e-5f);
#pragma unroll 4
    for (int i = 0; i < per; i++) {
        int c = lane + i * 32;
        float t = (v[i] - mean) * inv * gamma[c] + beta[c];
        if (do_gelu) t = gelu_exact(t);
        out[base + c] = t;
    }
}

// ---------------- CSR build ----------------
__global__ void hist_kernel(const int* __restrict__ dst, int* __restrict__ deg) {
    int e = blockIdx.x * blockDim.x + threadIdx.x;
    if (e < EE) atomicAdd(&deg[dst[e]], 1);
}

#define SCH 256
#define SNB ((NN + SCH - 1) / SCH)

__global__ void scan1_kernel(const int* __restrict__ deg, int* __restrict__ rowptr,
                             int* __restrict__ bsum) {
    __shared__ int s[SCH];
    int b = blockIdx.x, t = threadIdx.x;
    int i = b * SCH + t;
    int v = (i < NN) ? deg[i] : 0;
    s[t] = v; __syncthreads();
    for (int o = 1; o < SCH; o <<= 1) {
        int x = (t >= o) ? s[t - o] : 0;
        __syncthreads();
        s[t] += x;
        __syncthreads();
    }
    if (i < NN) rowptr[i] = s[t] - v;
    if (t == SCH - 1) bsum[b] = s[t];
}

__global__ void scan2_kernel(int* __restrict__ bsum) {
    __shared__ int s[256];
    int t = threadIdx.x;
    int v = (t < SNB) ? bsum[t] : 0;
    s[t] = v; __syncthreads();
    for (int o = 1; o < 256; o <<= 1) {
        int x = (t >= o) ? s[t - o] : 0;
        __syncthreads();
        s[t] += x;
        __syncthreads();
    }
    if (t < SNB) bsum[t] = s[t] - v;
}

__global__ void scan3_kernel(int* __restrict__ rowptr, const int* __restrict__ bsum,
                             int* __restrict__ cur) {
    int i = blockIdx.x * blockDim.x + threadIdx.x;
    if (i < NN) {
        int r = rowptr[i] + bsum[i / SCH];
        rowptr[i] = r;
        cur[i] = r;
    }
}

__global__ void scatter_kernel(const int* __restrict__ src, const int* __restrict__ dst,
                               int* __restrict__ cur, int* __restrict__ esrc) {
    int e = blockIdx.x * blockDim.x + threadIdx.x;
    if (e < EE) {
        int p = atomicAdd(&cur[dst[e]], 1);
        esrc[p] = src[e];
    }
}

// ---------------- fused GATv2 node kernel ----------------
// warp/node: online softmax over incoming edges (+self loop), weighted agg,
// then bias + LN + GELU + residual. Scores computed in-place (no score pass).
__global__ void gat_node_fused(const float* __restrict__ xl, const float* __restrict__ xr,
                               const int* __restrict__ rowptr, const int* __restrict__ rowend,
                               const int* __restrict__ esrc,
                               const float* __restrict__ att,
                               const float* __restrict__ colbias,
                               const float* __restrict__ gamma, const float* __restrict__ beta,
                               float* __restrict__ hbuf)
{
    int d = (blockIdx.x * blockDim.x + threadIdx.x) >> 5;
    int lane = threadIdx.x & 31;
    if (d >= NN) return;

    float pl[NH], pr[NH], at[NH], mh[NH], dh[NH], acc[NH];
    const float* pld = xl + (size_t)d * HIDW;
    const float* prd = xr + (size_t)d * HIDW;
#pragma unroll
    for (int h = 0; h < NH; h++) {
        pl[h] = pld[h * HD + lane];
        pr[h] = prd[h * HD + lane];
        at[h] = att[h * HD + lane];
    }
    // self-loop initializes the online-softmax state
#pragma unroll
    for (int h = 0; h < NH; h++) {
        float a = pl[h] + pr[h];
        a = a > 0.f ? a : 0.2f * a;
        float s = warpSum(a * at[h]);
        mh[h] = s; dh[h] = 1.f; acc[h] = pl[h];
    }
    int r0 = rowptr[d], r1 = rowend[d];
    for (int i = r0; i < r1; i++) {
        int s = esrc[i];
        const float* pv = xl + (size_t)s * HIDW;
        float xv[NH];
#pragma unroll
        for (int h = 0; h < NH; h++) xv[h] = pv[h * HD + lane];
#pragma unroll
        for (int h = 0; h < NH; h++) {
            float a = xv[h] + pr[h];
            a = a > 0.f ? a : 0.2f * a;
            float sc = warpSum(a * at[h]);
            if (sc <= mh[h]) {              // warp-uniform branch
                float e = expf(sc - mh[h]);
                dh[h] += e;
                acc[h] += e * xv[h];
            } else {
                float r = expf(mh[h] - sc);
                dh[h] = dh[h] * r + 1.f;
                acc[h] = acc[h] * r + xv[h];
                mh[h] = sc;
            }
        }
    }
    // normalize + bias, LN, GELU, residual
    float s1 = 0.f, s2 = 0.f, t[NH];
#pragma unroll
    for (int h = 0; h < NH; h++) {
        float v = acc[h] / (dh[h] + 1e-16f) + colbias[h * HD + lane];
        t[h] = v; s1 += v; s2 += v * v;
    }
    s1 = warpSum(s1); s2 = warpSum(s2);
    float mean = s1 / HIDW;
    float inv = rsqrtf(s2 / HIDW - mean * mean + 1e-5f);
    float* po = hbuf + (size_t)d * HIDW;
#pragma unroll
    for (int h = 0; h < NH; h++) {
        int c = h * HD + lane;
        float o = (t[h] - mean) * inv * gamma[c] + beta[c];
        po[c] += gelu_exact(o);
    }
}

// ---------------- fused TransformerConv node kernel ----------------
__global__ void tr_node_fused(const float* __restrict__ q, const float* __restrict__ kf,
                              const float* __restrict__ vf,
                              const int* __restrict__ rowptr, const int* __restrict__ rowend,
                              const int* __restrict__ esrc,
                              const float* __restrict__ skip,
                              const float* __restrict__ gamma, const float* __restrict__ beta,
                              float* __restrict__ hbuf)
{
    int d = (blockIdx.x * blockDim.x + threadIdx.x) >> 5;
    int lane = threadIdx.x & 31;
    if (d >= NN) return;

    float qr[NH], mh[NH], dh[NH], acc[NH];
    const float* pq = q + (size_t)d * HIDW;
#pragma unroll
    for (int h = 0; h < NH; h++) {
        qr[h] = pq[h * HD + lane];
        mh[h] = -INFINITY; dh[h] = 0.f; acc[h] = 0.f;
    }
    int r0 = rowptr[d], r1 = rowend[d];
    for (int i = r0; i < r1; i++) {
        int s = esrc[i];
        const float* pk = kf + (size_t)s * HIDW;
        const float* pv = vf + (size_t)s * HIDW;
        float kv[NH], vv[NH];
#pragma unroll
        for (int h = 0; h < NH; h++) { kv[h] = pk[h * HD + lane]; vv[h] = pv[h * HD + lane]; }
#pragma unroll
        for (int h = 0; h < NH; h++) {
            float sc = warpSum(qr[h] * kv[h]) * 0.17677669529663688f;
            if (sc <= mh[h]) {
                float e = expf(sc - mh[h]);
                dh[h] += e;
                acc[h] += e * vv[h];
            } else {
                float r = expf(mh[h] - sc);   // expf(-inf)=0 handles first edge
                dh[h] = dh[h] * r + 1.f;
                acc[h] = acc[h] * r + vv[h];
                mh[h] = sc;
            }
        }
    }
    const float* psk = skip + (size_t)d * HIDW;
    float s1 = 0.f, s2 = 0.f, t[NH];
#pragma unroll
    for (int h = 0; h < NH; h++) {
        float v = acc[h] / (dh[h] + 1e-16f) + psk[h * HD + lane];
        t[h] = v; s1 += v; s2 += v * v;
    }
    s1 = warpSum(s1); s2 = warpSum(s2);
    float mean = s1 / HIDW;
    float inv = rsqrtf(s2 / HIDW - mean * mean + 1e-5f);
    float* po = hbuf + (size_t)d * HIDW;
#pragma unroll
    for (int h = 0; h < NH; h++) {
        int c = h * HD + lane;
        po[c] += (t[h] - mean) * inv * gamma[c] + beta[c];
    }
}

// ---------------- pooling: block per graph, batch is sorted ----------------
__global__ void pool_kernel(const float* __restrict__ h, const int* __restrict__ batch,
                            float* __restrict__ ge)
{
    int g = blockIdx.x;
    int f = threadIdx.x;      // 256
    __shared__ int slo, shi;
    if (f == 0) {
        int lo = 0, hi = NN;
        while (lo < hi) { int mid = (lo + hi) >> 1; if (batch[mid] < g) lo = mid + 1; else hi = mid; }
        slo = lo;
        hi = NN;
        while (lo < hi) { int mid = (lo + hi) >> 1; if (batch[mid] < g + 1) lo = mid + 1; else hi = mid; }
        shi = lo;
    }
    __syncthreads();
    int lo = slo, hi = shi;
    float s = 0.f, mx = -INFINITY;
    for (int n = lo; n < hi; n++) {
        float v = h[(size_t)n * HIDW + f];
        s += v; mx = fmaxf(mx, v);
    }
    float cnt = (float)(hi - lo);
    ge[(size_t)g * (2 * HIDW) + f] = s / fmaxf(cnt, 1.f);
    ge[(size_t)g * (2 * HIDW) + HIDW + f] = isfinite(mx) ? mx : 0.f;
}

// ---------------- host orchestration ----------------
extern "C" void kernel_launch(void* const* d_in, const int* in_sizes, int n_in,
                              void* d_out, int out_size)
{
    const float* x       = (const float*)d_in[0];
    const int*   ei      = (const int*)  d_in[1];
    const int*   batch   = (const int*)  d_in[2];
    const float* in_W    = (const float*)d_in[3];
    const float* in_b    = (const float*)d_in[4];
    const float* in_ln_g = (const float*)d_in[5];
    const float* in_ln_b = (const float*)d_in[6];
    const float* gat_Wl  = (const float*)d_in[7];
    const float* gat_bl  = (const float*)d_in[8];
    const float* gat_Wr  = (const float*)d_in[9];
    const float* gat_br  = (const float*)d_in[10];
    const float* gat_att = (const float*)d_in[11];
    const float* gat_bias= (const float*)d_in[12];
    const float* gat_ln_g= (const float*)d_in[13];
    const float* gat_ln_b= (const float*)d_in[14];
    const float* tr_Wq   = (const float*)d_in[15];
    const float* tr_bq   = (const float*)d_in[16];
    const float* tr_Wk   = (const float*)d_in[17];
    const float* tr_bk   = (const float*)d_in[18];
    const float* tr_Wv   = (const float*)d_in[19];
    const float* tr_bv   = (const float*)d_in[20];
    const float* tr_Wskip= (const float*)d_in[21];
    const float* tr_bskip= (const float*)d_in[22];
    const float* tr_ln_g = (const float*)d_in[23];
    const float* tr_ln_b = (const float*)d_in[24];
    const float* out_W   = (const float*)d_in[25];
    const float* out_b   = (const float*)d_in[26];
    const float* out_ln_g= (const float*)d_in[27];
    const float* out_ln_b= (const float*)d_in[28];

    const int* src = ei;
    const int* dst = ei + EE;

    float *h, *b1, *b2, *b3, *b4, *ge, *go;
    int *deg, *rowptr, *cur, *bsum, *esrc;
    cudaGetSymbolAddress((void**)&h,   g_h);
    cudaGetSymbolAddress((void**)&b1,  g_b1);
    cudaGetSymbolAddress((void**)&b2,  g_b2);
    cudaGetSymbolAddress((void**)&b3,  g_b3);
    cudaGetSymbolAddress((void**)&b4,  g_b4);
    cudaGetSymbolAddress((void**)&ge,  g_ge);
    cudaGetSymbolAddress((void**)&go,  g_go);
    cudaGetSymbolAddress((void**)&deg,   g_deg);
    cudaGetSymbolAddress((void**)&rowptr,g_rowptr);
    cudaGetSymbolAddress((void**)&cur,   g_cur);
    cudaGetSymbolAddress((void**)&bsum,  g_bsum);
    cudaGetSymbolAddress((void**)&esrc,  g_esrc);

    const int ROW_WARPS_N = (NN * 32 + 255) / 256;
    const dim3 GEMM_GRID(HIDW / GBN, (NN + GBM - 1) / GBM);

    // ---- CSR build (by destination) ----
    cudaMemsetAsync(deg, 0, NN * sizeof(int));
    hist_kernel   <<<(EE + 255) / 256, 256>>>(dst, deg);
    scan1_kernel  <<<SNB, SCH>>>(deg, rowptr, bsum);
    scan2_kernel  <<<1, 256>>>(bsum);
    scan3_kernel  <<<(NN + 255) / 256, 256>>>(rowptr, bsum, cur);
    scatter_kernel<<<(EE + 255) / 256, 256>>>(src, dst, cur, esrc);

    // ---- input embedding: h = gelu(LN(x @ in_W + in_b)) ----
    gemm_tf32<<<GEMM_GRID, 256>>>(x, in_W, in_b, b1, NN, FIN, HIDW);
    ln_act_kernel<<<ROW_WARPS_N, 256>>>(b1, in_ln_g, in_ln_b, h, NN, HIDW, 1);

    // ---- 5 GATv2 layers ----
    for (int l = 0; l < NL; l++) {
        const float* Wl = gat_Wl + (size_t)l * HIDW * HIDW;
        const float* Wr = gat_Wr + (size_t)l * HIDW * HIDW;
        gemm_tf32<<<GEMM_GRID, 256>>>(h, Wl, gat_bl + l * HIDW, b1, NN, HIDW, HIDW);
        gemm_tf32<<<GEMM_GRID, 256>>>(h, Wr, gat_br + l * HIDW, b2, NN, HIDW, HIDW);
        gat_node_fused<<<ROW_WARPS_N, 256>>>(b1, b2, rowptr, cur, esrc,
                                             gat_att + (size_t)l * NH * HD,
                                             gat_bias + l * HIDW,
                                             gat_ln_g + l * HIDW, gat_ln_b + l * HIDW,
                                             h);
    }

    // ---- TransformerConv ----
    gemm_tf32<<<GEMM_GRID, 256>>>(h, tr_Wq, tr_bq, b1, NN, HIDW, HIDW);
    gemm_tf32<<<GEMM_GRID, 256>>>(h, tr_Wk, tr_bk, b2, NN, HIDW, HIDW);
    gemm_tf32<<<GEMM_GRID, 256>>>(h, tr_Wv, tr_bv, b3, NN, HIDW, HIDW);
    gemm_tf32<<<GEMM_GRID, 256>>>(h, tr_Wskip, tr_bskip, b4, NN, HIDW, HIDW);
    tr_node_fused<<<ROW_WARPS_N, 256>>>(b1, b2, b3, rowptr, cur, esrc,
                                        b4, tr_ln_g, tr_ln_b, h);

    // ---- global mean + max pool (batch sorted; block per graph) ----
    pool_kernel<<<GG, 256>>>(h, batch, ge);

    // ---- output projection: gelu(LN(ge @ out_W + out_b)) ----
    gemm_tf32<<<dim3(2 * HIDW / GBN, (GG + GBM - 1) / GBM), 256>>>(ge, out_W, out_b, go,
                                                                   GG, 2 * HIDW, 2 * HIDW);
    ln_act_kernel<<<(GG * 32 + 255) / 256, 256>>>(go, out_ln_g, out_ln_b,
                                                  (float*)d_out, GG, 2 * HIDW, 1);
}